// round 5
// baseline (speedup 1.0000x reference)
#include <cuda_runtime.h>
#include <cuda_bf16.h>

#define WEIGHT_POSITIVE 0.1f

// 148 SMs x 8 CTAs/SM (256 thr, 26 regs -> thread-limited at 8) = one balanced wave.
static constexpr int BLOCKS  = 148 * 8;   // 1184
static constexpr int THREADS = 256;

// Scratch (no device allocation allowed anywhere).
__device__ float        g_partials[BLOCKS];
__device__ unsigned int g_ticket = 0;

__device__ __forceinline__ float elem(float p, int t)
{
    float d   = p - (float)t;
    bool  mis = (p >= 0.5f) != (t == 1);
    return (mis ? (1.0f + WEIGHT_POSITIVE) : 1.0f) * d * d;
}

__global__ __launch_bounds__(THREADS)
void wmse_fused_kernel(const float4* __restrict__ pred4,
                       const int4*   __restrict__ tgt4,
                       float* __restrict__ out,
                       int n_vec, float inv_n)
{
    const int stride = gridDim.x * blockDim.x;

    float sum = 0.0f;
    for (int i = blockIdx.x * blockDim.x + threadIdx.x; i < n_vec; i += stride) {
        float4 p = __ldg(&pred4[i]);
        int4   t = __ldg(&tgt4[i]);
        sum += elem(p.x, t.x) + elem(p.y, t.y) + elem(p.z, t.z) + elem(p.w, t.w);
    }

    // Warp reduce
    #pragma unroll
    for (int off = 16; off > 0; off >>= 1)
        sum += __shfl_down_sync(0xFFFFFFFFu, sum, off);

    __shared__ float warp_sums[THREADS / 32];
    __shared__ bool  is_last;
    int lane = threadIdx.x & 31;
    int wid  = threadIdx.x >> 5;
    if (lane == 0) warp_sums[wid] = sum;
    __syncthreads();

    if (wid == 0) {
        float s = (lane < THREADS / 32) ? warp_sums[lane] : 0.0f;
        #pragma unroll
        for (int off = 16; off > 0; off >>= 1)
            s += __shfl_down_sync(0xFFFFFFFFu, s, off);
        if (lane == 0) {
            g_partials[blockIdx.x] = s;
            __threadfence();
            unsigned int t = atomicAdd(&g_ticket, 1u);
            is_last = (t == (unsigned int)(gridDim.x - 1));
        }
    }
    __syncthreads();

    // Last block to finish sums all partials in a FIXED order -> deterministic.
    if (is_last) {
        float fs = 0.0f;
        for (int k = threadIdx.x; k < BLOCKS; k += THREADS)
            fs += *((volatile float*)&g_partials[k]);

        #pragma unroll
        for (int off = 16; off > 0; off >>= 1)
            fs += __shfl_down_sync(0xFFFFFFFFu, fs, off);

        if (lane == 0) warp_sums[wid] = fs;
        __syncthreads();

        if (wid == 0) {
            float s = (lane < THREADS / 32) ? warp_sums[lane] : 0.0f;
            #pragma unroll
            for (int off = 16; off > 0; off >>= 1)
                s += __shfl_down_sync(0xFFFFFFFFu, s, off);
            if (lane == 0) {
                out[0] = s * inv_n;
                g_ticket = 0;   // reset for next graph replay (deterministic)
            }
        }
    }
}

extern "C" void kernel_launch(void* const* d_in, const int* in_sizes, int n_in,
                              void* d_out, int out_size)
{
    const float* pred = (const float*)d_in[0];
    const int*   tgt  = (const int*)d_in[1];
    float*       out  = (float*)d_out;
    int n = in_sizes[0];

    int n_vec = n / 4;  // N = 2^25, divisible by 4

    wmse_fused_kernel<<<BLOCKS, THREADS>>>((const float4*)pred, (const int4*)tgt,
                                           out, n_vec, 1.0f / (float)n);
}